// round 1
// baseline (speedup 1.0000x reference)
#include <cuda_runtime.h>

#define B_  64
#define T_  120
#define P_  25
#define D_  128
#define L_  2
#define PD_ (P_*D_)      // 3200
#define NBT (B_*T_)      // 7680
#define PP_ (P_*P_)      // 625

// shared memory layout (float offsets)
#define OFF_W    0
#define OFF_H    (2*D_*D_)          // 32768
#define OFF_Y    (OFF_H + PD_)      // 35968
#define OFF_DIST (OFF_Y + PD_)      // 39168
#define OFF_KNN  (OFF_DIST + 640)   // 39808 (ints live here)
#define SMEM_FLOATS (OFF_KNN + 128) // 39936
#define SMEM_BYTES  (SMEM_FLOATS * 4)

// scratch: h in [B*T, P*D] layout, updated in place by the main kernel
__device__ float g_ht[(size_t)NBT * PD_];

// ---------------------------------------------------------------------------
// Transpose x[B,P*D,T] -> g_ht[B,T,P*D]
// ---------------------------------------------------------------------------
__global__ void k_tin(const float* __restrict__ x) {
    __shared__ float tile[32][33];
    const int b   = blockIdx.z;
    const int pd0 = blockIdx.x * 32;
    const int t0  = blockIdx.y * 32;
    const int tx = threadIdx.x, ty = threadIdx.y;
#pragma unroll
    for (int i = ty; i < 32; i += 8) {
        int t = t0 + tx;
        if (t < T_) tile[i][tx] = x[((size_t)b * PD_ + pd0 + i) * T_ + t];
    }
    __syncthreads();
#pragma unroll
    for (int i = ty; i < 32; i += 8) {
        int t = t0 + i;
        if (t < T_) g_ht[((size_t)b * T_ + t) * PD_ + pd0 + tx] = tile[tx][i];
    }
}

// ---------------------------------------------------------------------------
// Transpose g_ht[B,T,P*D] -> out[B,P*D,T]
// ---------------------------------------------------------------------------
__global__ void k_tout(float* __restrict__ out) {
    __shared__ float tile[32][33];
    const int b   = blockIdx.z;
    const int pd0 = blockIdx.x * 32;
    const int t0  = blockIdx.y * 32;
    const int tx = threadIdx.x, ty = threadIdx.y;
#pragma unroll
    for (int i = ty; i < 32; i += 8) {
        int t = t0 + i;
        if (t < T_) tile[i][tx] = g_ht[((size_t)b * T_ + t) * PD_ + pd0 + tx];
    }
    __syncthreads();
#pragma unroll
    for (int i = ty; i < 32; i += 8) {
        int t = t0 + tx;
        if (t < T_) out[((size_t)b * PD_ + pd0 + i) * T_ + t] = tile[tx][i];
    }
}

// ---------------------------------------------------------------------------
// Main fused GCN kernel: persistent CTAs, one (b,t) tile at a time.
//   per bt: knn(4) from distances, then for each layer:
//     y = h @ W_l ; z = 0.2*(y + sum_nb y) + bias ; relu ; layernorm ; h += z
// ---------------------------------------------------------------------------
__global__ __launch_bounds__(256, 1)
void k_main(const float* __restrict__ dist_g,
            const float* __restrict__ w_g,
            const float* __restrict__ bias_g,
            const float* __restrict__ gamma_g,
            const float* __restrict__ beta_g)
{
    extern __shared__ float sm[];
    float* Ws = sm + OFF_W;
    float* hs = sm + OFF_H;
    float* ys = sm + OFF_Y;
    float* ds = sm + OFF_DIST;
    int*   kn = (int*)(sm + OFF_KNN);

    const int tid = threadIdx.x;

    // stage both weight matrices (32768 floats) into smem once per CTA
    for (int i = tid; i < 2 * D_ * D_; i += 256) Ws[i] = w_g[i];

    // GEMM thread mapping: 4 p-groups x 64 e-pairs
    const int g  = tid >> 6;            // 0..3
    const int e2 = tid & 63;            // e = 2*e2, 2*e2+1
    const int p0 = (g == 0) ? 0 : 1 + 6 * g;   // 0,7,13,19
    const int pc = (g == 0) ? 7 : 6;
    const int warp = tid >> 5, lane = tid & 31;

    for (int bt = blockIdx.x; bt < NBT; bt += gridDim.x) {
        __syncthreads();   // protect smem reuse from previous iteration
        for (int i = tid; i < PP_; i += 256) ds[i] = dist_g[(size_t)bt * PP_ + i];
        for (int i = tid; i < PD_; i += 256) hs[i] = g_ht[(size_t)bt * PD_ + i];
        __syncthreads();

        // ---- kNN (4 smallest, self excluded, ties -> lower index) ----
        if (tid < P_) {
            const int p = tid;
            float bv[4] = {1e30f, 1e30f, 1e30f, 1e30f};
            int   bi[4] = {0, 0, 0, 0};
            for (int q = 0; q < P_; ++q) {
                if (q == p) continue;
                float dv = ds[p * P_ + q];
                if (dv < bv[3]) {
                    bv[3] = dv; bi[3] = q;
#pragma unroll
                    for (int k = 3; k > 0; --k) {
                        if (bv[k] < bv[k - 1]) {
                            float tv = bv[k]; bv[k] = bv[k - 1]; bv[k - 1] = tv;
                            int   ti = bi[k]; bi[k] = bi[k - 1]; bi[k - 1] = ti;
                        }
                    }
                }
            }
#pragma unroll
            for (int k = 0; k < 4; ++k) kn[p * 4 + k] = bi[k];
        }
        __syncthreads();

#pragma unroll
        for (int l = 0; l < L_; ++l) {
            const float* Wl = Ws + l * D_ * D_;

            // ---- y = h @ W_l  (25x128x128, fp32 FFMA) ----
            float acc[7][2];
#pragma unroll
            for (int pp = 0; pp < 7; ++pp) { acc[pp][0] = 0.f; acc[pp][1] = 0.f; }

#pragma unroll 4
            for (int d4 = 0; d4 < D_ / 4; ++d4) {
                const int d = d4 * 4;
                float2 w0 = *(const float2*)&Wl[(d + 0) * D_ + 2 * e2];
                float2 w1 = *(const float2*)&Wl[(d + 1) * D_ + 2 * e2];
                float2 w2 = *(const float2*)&Wl[(d + 2) * D_ + 2 * e2];
                float2 w3 = *(const float2*)&Wl[(d + 3) * D_ + 2 * e2];
#pragma unroll
                for (int pp = 0; pp < 7; ++pp) {
                    if (pp < pc) {
                        float4 hv = *(const float4*)&hs[(p0 + pp) * D_ + d];
                        acc[pp][0] = fmaf(hv.x, w0.x, acc[pp][0]);
                        acc[pp][1] = fmaf(hv.x, w0.y, acc[pp][1]);
                        acc[pp][0] = fmaf(hv.y, w1.x, acc[pp][0]);
                        acc[pp][1] = fmaf(hv.y, w1.y, acc[pp][1]);
                        acc[pp][0] = fmaf(hv.z, w2.x, acc[pp][0]);
                        acc[pp][1] = fmaf(hv.z, w2.y, acc[pp][1]);
                        acc[pp][0] = fmaf(hv.w, w3.x, acc[pp][0]);
                        acc[pp][1] = fmaf(hv.w, w3.y, acc[pp][1]);
                    }
                }
            }
#pragma unroll
            for (int pp = 0; pp < 7; ++pp)
                if (pp < pc)
                    *(float2*)&ys[(p0 + pp) * D_ + 2 * e2] =
                        make_float2(acc[pp][0], acc[pp][1]);
            __syncthreads();

            // ---- graph aggregate (adj/5) + bias + relu -> registers ----
            float2 bia = *(const float2*)&bias_g[l * D_ + 2 * e2];
            float zz[7][2];
#pragma unroll
            for (int pp = 0; pp < 7; ++pp) {
                if (pp < pc) {
                    const int p = p0 + pp;
                    float sx = ys[p * D_ + 2 * e2];
                    float sy = ys[p * D_ + 2 * e2 + 1];
#pragma unroll
                    for (int j = 0; j < 4; ++j) {
                        int nb = kn[p * 4 + j];
                        sx += ys[nb * D_ + 2 * e2];
                        sy += ys[nb * D_ + 2 * e2 + 1];
                    }
                    zz[pp][0] = fmaxf(0.2f * sx + bia.x, 0.f);
                    zz[pp][1] = fmaxf(0.2f * sy + bia.y, 0.f);
                }
            }
            __syncthreads();
#pragma unroll
            for (int pp = 0; pp < 7; ++pp)
                if (pp < pc)
                    *(float2*)&ys[(p0 + pp) * D_ + 2 * e2] =
                        make_float2(zz[pp][0], zz[pp][1]);
            __syncthreads();

            // ---- layernorm over D + residual into hs (warp per row) ----
            float4 g4 = *(const float4*)&gamma_g[l * D_ + lane * 4];
            float4 b4 = *(const float4*)&beta_g[l * D_ + lane * 4];
            for (int p = warp; p < P_; p += 8) {
                float4 v = *(const float4*)&ys[p * D_ + lane * 4];
                float s = v.x + v.y + v.z + v.w;
                float q = v.x * v.x + v.y * v.y + v.z * v.z + v.w * v.w;
#pragma unroll
                for (int o = 16; o > 0; o >>= 1) {
                    s += __shfl_xor_sync(0xffffffffu, s, o);
                    q += __shfl_xor_sync(0xffffffffu, q, o);
                }
                float mu  = s * (1.0f / D_);
                float var = q * (1.0f / D_) - mu * mu;
                float rs  = rsqrtf(var + 1e-5f);
                float4 hv = *(const float4*)&hs[p * D_ + lane * 4];
                hv.x += (v.x - mu) * rs * g4.x + b4.x;
                hv.y += (v.y - mu) * rs * g4.y + b4.y;
                hv.z += (v.z - mu) * rs * g4.z + b4.z;
                hv.w += (v.w - mu) * rs * g4.w + b4.w;
                *(float4*)&hs[p * D_ + lane * 4] = hv;
            }
            __syncthreads();
        }

        // write back final h for this bt
        for (int i = tid; i < PD_; i += 256) g_ht[(size_t)bt * PD_ + i] = hs[i];
    }
}

// ---------------------------------------------------------------------------
extern "C" void kernel_launch(void* const* d_in, const int* in_sizes, int n_in,
                              void* d_out, int out_size)
{
    const float* x     = (const float*)d_in[0];
    const float* dist  = (const float*)d_in[1];
    const float* w     = (const float*)d_in[2];
    const float* bias  = (const float*)d_in[3];
    const float* gamma = (const float*)d_in[4];
    const float* beta  = (const float*)d_in[5];
    float* out = (float*)d_out;

    cudaFuncSetAttribute(k_main, cudaFuncAttributeMaxDynamicSharedMemorySize,
                         SMEM_BYTES);

    int sms = 148;
    cudaDeviceGetAttribute(&sms, cudaDevAttrMultiProcessorCount, 0);

    dim3 tb(32, 8);
    dim3 tg(PD_ / 32, (T_ + 31) / 32, B_);

    k_tin<<<tg, tb>>>(x);
    k_main<<<sms, 256, SMEM_BYTES>>>(dist, w, bias, gamma, beta);
    k_tout<<<tg, tb>>>(out);
}

// round 4
// speedup vs baseline: 2.1227x; 2.1227x over previous
#include <cuda_runtime.h>
#include <cstdint>

#define B_  64
#define T_  120
#define P_  25
#define D_  128
#define PD_ 3200
#define NBT 7680
#define TILES 1536        // NBT/5, 5 bt per tile -> 125 rows padded to 128
#define ROWS_V 125
#define HS 132            // hy stride in floats

// ---- smem byte offsets ----
#define SO_W   0                    // packed W fragments: 2*16384*4 = 131072
#define SO_HY  131072               // 128*132*4 = 67584 (h A-operand / y staging)
#define SO_DS  198656               // 5*625*4 = 12500
#define SO_KN  211156               // 125*4*4 = 2000
#define SO_BB  213168               // 256*4 (16-aligned)
#define SO_GG  214192               // 256*4
#define SO_BE  215216               // 256*4
#define SMEM_MAIN 216240

// scratch: h in [B*T, P*D] layout
__device__ float g_ht[(size_t)NBT * PD_];

static __device__ __forceinline__ uint32_t f2tf32(float x){
    uint32_t u; asm("cvt.rna.tf32.f32 %0, %1;" : "=r"(u) : "f"(x)); return u;
}
static __device__ __forceinline__ void mma8(float* c, uint32_t a0, uint32_t a1,
                                            uint32_t a2, uint32_t a3,
                                            uint32_t b0, uint32_t b1){
    asm volatile("mma.sync.aligned.m16n8k8.row.col.f32.tf32.tf32.f32 "
        "{%0,%1,%2,%3}, {%4,%5,%6,%7}, {%8,%9}, {%0,%1,%2,%3};"
        : "+f"(c[0]), "+f"(c[1]), "+f"(c[2]), "+f"(c[3])
        : "r"(a0), "r"(a1), "r"(a2), "r"(a3), "r"(b0), "r"(b1));
}

// ---------------------------------------------------------------------------
__global__ void k_tin(const float* __restrict__ x) {
    __shared__ float tile[32][33];
    const int b   = blockIdx.z;
    const int pd0 = blockIdx.x * 32;
    const int t0  = blockIdx.y * 32;
    const int tx = threadIdx.x, ty = threadIdx.y;
#pragma unroll
    for (int i = ty; i < 32; i += 8) {
        int t = t0 + tx;
        if (t < T_) tile[i][tx] = x[((size_t)b * PD_ + pd0 + i) * T_ + t];
    }
    __syncthreads();
#pragma unroll
    for (int i = ty; i < 32; i += 8) {
        int t = t0 + i;
        if (t < T_) g_ht[((size_t)b * T_ + t) * PD_ + pd0 + tx] = tile[tx][i];
    }
}

__global__ void k_tout(float* __restrict__ out) {
    __shared__ float tile[32][33];
    const int b   = blockIdx.z;
    const int pd0 = blockIdx.x * 32;
    const int t0  = blockIdx.y * 32;
    const int tx = threadIdx.x, ty = threadIdx.y;
#pragma unroll
    for (int i = ty; i < 32; i += 8) {
        int t = t0 + i;
        if (t < T_) tile[i][tx] = g_ht[((size_t)b * T_ + t) * PD_ + pd0 + tx];
    }
    __syncthreads();
#pragma unroll
    for (int i = ty; i < 32; i += 8) {
        int t = t0 + tx;
        if (t < T_) out[((size_t)b * PD_ + pd0 + i) * T_ + t] = tile[tx][i];
    }
}

// ---------------------------------------------------------------------------
// Main fused GCN: persistent CTAs, 5 bt/tile, warp-level tf32 mma.sync GEMM.
// ---------------------------------------------------------------------------
__global__ __launch_bounds__(256, 1)
void k_main(const float* __restrict__ dist_g,
            const float* __restrict__ w_g,
            const float* __restrict__ bias_g,
            const float* __restrict__ gamma_g,
            const float* __restrict__ beta_g)
{
    extern __shared__ char smc[];
    float* Ws = (float*)(smc + SO_W);
    float* hy = (float*)(smc + SO_HY);
    float* ds = (float*)(smc + SO_DS);
    int*   kn = (int*)  (smc + SO_KN);
    float* bb = (float*)(smc + SO_BB);
    float* gg = (float*)(smc + SO_GG);
    float* be = (float*)(smc + SO_BE);

    const int tid  = threadIdx.x;
    const int warp = tid >> 5, lane = tid & 31;
    const int qr = lane >> 2;          // 0..7
    const int qc = lane & 3;           // 0..3
    const int R0 = warp * 16 + qr;     // first owned row (< 125 always)
    const int R1 = R0 + 8;             // second owned row (may be pad)
    const bool v1 = (R1 < ROWS_V);

    // ---- pack both weight matrices into fragment-order float4s ----
    // float4 idx = ((l*16+kt)*8+np)*32 + qr*4 + qc ; components:
    //   x = W[8kt+qc][8np+qr], y = W[8kt+qc+4][8np+qr],
    //   z = W[8kt+qc][64+8np+qr], w = W[8kt+qc+4][64+8np+qr]   (tf32-rounded)
    for (int i = tid; i < 2 * D_ * D_; i += 256) {
        int l = i >> 14, k = (i >> 7) & 127, n = i & 127;
        int kt = k >> 3, c = k & 3, b1b = (k >> 2) & 1;
        int g = n & 7, np = (n >> 3) & 7, j = ((n >> 6) << 1) | b1b;
        uint32_t v = f2tf32(w_g[i]);
        ((uint32_t*)Ws)[((((l*16 + kt)*8 + np)*32 + g*4 + c) << 2) + j] = v;
    }
    for (int i = tid; i < 256; i += 256) {
        bb[i] = bias_g[i]; gg[i] = gamma_g[i]; be[i] = beta_g[i];
    }

    float hres[16][4];   // full-precision residual h, thread-owned
    float acc[16][4];    // mma accumulators / z scratch

    for (int tile = blockIdx.x; tile < TILES; tile += gridDim.x) {
        __syncthreads();   // guard smem reuse

        // stage distances
        for (int i = tid; i < 5 * P_ * P_; i += 256)
            ds[i] = dist_g[(size_t)tile * 3125 + i];

        const size_t hb = (size_t)tile * 16000;
        // stage h0 (tf32-rounded) into hy, coalesced; zero pad rows
        for (int i = tid; i < 128 * 128; i += 256) {
            int row = i >> 7, col = i & 127;
            float v = (row < ROWS_V) ? g_ht[hb + (size_t)row * 128 + col] : 0.f;
            ((uint32_t*)hy)[row * HS + col] = f2tf32(v);
        }
        // exact h0 residual into registers (thread-owned cols 8nt+2qc,+1)
#pragma unroll
        for (int nt = 0; nt < 16; ++nt) {
            int col = 8 * nt + 2 * qc;
            float2 a = *(const float2*)&g_ht[hb + (size_t)R0 * 128 + col];
            hres[nt][0] = a.x; hres[nt][1] = a.y;
            if (v1) {
                float2 b = *(const float2*)&g_ht[hb + (size_t)R1 * 128 + col];
                hres[nt][2] = b.x; hres[nt][3] = b.y;
            } else { hres[nt][2] = 0.f; hres[nt][3] = 0.f; }
        }
        __syncthreads();

        // kNN (4 smallest, self excluded)
        if (tid < ROWS_V) {
            const int p = tid % 25;
            const float* dp = ds + (tid / 25) * 625 + p * 25;
            float bv0 = 1e30f, bv1 = 1e30f, bv2 = 1e30f, bv3 = 1e30f;
            int bi0 = 0, bi1 = 0, bi2 = 0, bi3 = 0;
            for (int q = 0; q < 25; ++q) {
                if (q == p) continue;
                float dv = dp[q];
                if (dv < bv3) {
                    bv3 = dv; bi3 = q;
                    if (bv3 < bv2) { float t=bv3; bv3=bv2; bv2=t; int ti=bi3; bi3=bi2; bi2=ti; }
                    if (bv2 < bv1) { float t=bv2; bv2=bv1; bv1=t; int ti=bi2; bi2=bi1; bi1=ti; }
                    if (bv1 < bv0) { float t=bv1; bv1=bv0; bv0=t; int ti=bi1; bi1=bi0; bi0=ti; }
                }
            }
            const int base = (tid / 25) * 25;
            kn[tid*4+0] = base + bi0; kn[tid*4+1] = base + bi1;
            kn[tid*4+2] = base + bi2; kn[tid*4+3] = base + bi3;
        }
        __syncthreads();

#pragma unroll
        for (int l = 0; l < 2; ++l) {
            // ---- y = h @ W_l via mma.sync tf32 ----
#pragma unroll
            for (int nt = 0; nt < 16; ++nt)
#pragma unroll
                for (int j = 0; j < 4; ++j) acc[nt][j] = 0.f;

            const uint32_t* hyu = (const uint32_t*)hy;
            const float4* wf = (const float4*)Ws + (size_t)(l*16)*8*32 + qr*4 + qc;
#pragma unroll
            for (int kt = 0; kt < 16; ++kt) {
                uint32_t a0 = hyu[R0 * HS + 8*kt + qc];
                uint32_t a1 = hyu[R1 * HS + 8*kt + qc];
                uint32_t a2 = hyu[R0 * HS + 8*kt + qc + 4];
                uint32_t a3 = hyu[R1 * HS + 8*kt + qc + 4];
                const float4* wk = wf + kt*8*32;
#pragma unroll
                for (int np = 0; np < 8; ++np) {
                    float4 b = wk[np*32];
                    mma8(acc[np],     a0, a1, a2, a3,
                         __float_as_uint(b.x), __float_as_uint(b.y));
                    mma8(acc[np + 8], a0, a1, a2, a3,
                         __float_as_uint(b.z), __float_as_uint(b.w));
                }
            }
            __syncthreads();   // all A reads done; hy becomes y buffer

            // stage y into hy
#pragma unroll
            for (int nt = 0; nt < 16; ++nt) {
                int col = 8*nt + 2*qc;
                *(float2*)&hy[R0 * HS + col] = make_float2(acc[nt][0], acc[nt][1]);
                *(float2*)&hy[R1 * HS + col] = make_float2(acc[nt][2], acc[nt][3]);
            }
            __syncthreads();

            // gather (self + 4 nb)/5 + bias + relu; LN stats per row
            const int kb0 = R0 * 4;
            const int kb1 = (v1 ? R1 : 0) * 4;
            const int n00 = kn[kb0+0], n01 = kn[kb0+1], n02 = kn[kb0+2], n03 = kn[kb0+3];
            const int n10 = kn[kb1+0], n11 = kn[kb1+1], n12 = kn[kb1+2], n13 = kn[kb1+3];
            float S0 = 0.f, Q0 = 0.f, S1 = 0.f, Q1 = 0.f;
#pragma unroll
            for (int nt = 0; nt < 16; ++nt) {
                int col = 8*nt + 2*qc;
                float2 bi2v = *(const float2*)&bb[l*128 + col];
                float2 e0 = *(const float2*)&hy[n00*HS + col];
                float2 e1 = *(const float2*)&hy[n01*HS + col];
                float2 e2 = *(const float2*)&hy[n02*HS + col];
                float2 e3 = *(const float2*)&hy[n03*HS + col];
                float z0 = fmaxf(fmaf(0.2f, acc[nt][0]+e0.x+e1.x+e2.x+e3.x, bi2v.x), 0.f);
                float z1 = fmaxf(fmaf(0.2f, acc[nt][1]+e0.y+e1.y+e2.y+e3.y, bi2v.y), 0.f);
                float2 f0 = *(const float2*)&hy[n10*HS + col];
                float2 f1 = *(const float2*)&hy[n11*HS + col];
                float2 f2 = *(const float2*)&hy[n12*HS + col];
                float2 f3 = *(const float2*)&hy[n13*HS + col];
                float z2 = fmaxf(fmaf(0.2f, acc[nt][2]+f0.x+f1.x+f2.x+f3.x, bi2v.x), 0.f);
                float z3 = fmaxf(fmaf(0.2f, acc[nt][3]+f0.y+f1.y+f2.y+f3.y, bi2v.y), 0.f);
                acc[nt][0] = z0; acc[nt][1] = z1; acc[nt][2] = z2; acc[nt][3] = z3;
                S0 += z0 + z1; Q0 = fmaf(z0, z0, Q0); Q0 = fmaf(z1, z1, Q0);
                S1 += z2 + z3; Q1 = fmaf(z2, z2, Q1); Q1 = fmaf(z3, z3, Q1);
            }
            // quad reduce (row's 128 cols live in lanes qc=0..3 of one quad)
            S0 += __shfl_xor_sync(0xffffffffu, S0, 1); S0 += __shfl_xor_sync(0xffffffffu, S0, 2);
            Q0 += __shfl_xor_sync(0xffffffffu, Q0, 1); Q0 += __shfl_xor_sync(0xffffffffu, Q0, 2);
            S1 += __shfl_xor_sync(0xffffffffu, S1, 1); S1 += __shfl_xor_sync(0xffffffffu, S1, 2);
            Q1 += __shfl_xor_sync(0xffffffffu, Q1, 1); Q1 += __shfl_xor_sync(0xffffffffu, Q1, 2);
            float mu0 = S0 * (1.f/128.f), var0 = Q0 * (1.f/128.f) - mu0*mu0;
            float mu1 = S1 * (1.f/128.f), var1 = Q1 * (1.f/128.f) - mu1*mu1;
            float rs0 = rsqrtf(var0 + 1e-5f), rs1 = rsqrtf(var1 + 1e-5f);
#pragma unroll
            for (int nt = 0; nt < 16; ++nt) {
                int col = 8*nt + 2*qc;
                float2 g2 = *(const float2*)&gg[l*128 + col];
                float2 b2 = *(const float2*)&be[l*128 + col];
                hres[nt][0] += (acc[nt][0] - mu0) * rs0 * g2.x + b2.x;
                hres[nt][1] += (acc[nt][1] - mu0) * rs0 * g2.y + b2.y;
                hres[nt][2] += (acc[nt][2] - mu1) * rs1 * g2.x + b2.x;
                hres[nt][3] += (acc[nt][3] - mu1) * rs1 * g2.y + b2.y;
            }
            __syncthreads();   // gather reads done; hy may be overwritten

            if (l == 0) {
                // store h1 (tf32-rounded) as next layer's A; keep pad rows zero
#pragma unroll
                for (int nt = 0; nt < 16; ++nt) {
                    int col = 8*nt + 2*qc;
                    ((uint32_t*)hy)[R0*HS + col]     = f2tf32(hres[nt][0]);
                    ((uint32_t*)hy)[R0*HS + col + 1] = f2tf32(hres[nt][1]);
                    ((uint32_t*)hy)[R1*HS + col]     = v1 ? f2tf32(hres[nt][2]) : 0u;
                    ((uint32_t*)hy)[R1*HS + col + 1] = v1 ? f2tf32(hres[nt][3]) : 0u;
                }
                __syncthreads();
            }
        }

        // write back final h (exact, from registers)
#pragma unroll
        for (int nt = 0; nt < 16; ++nt) {
            int col = 8*nt + 2*qc;
            *(float2*)&g_ht[hb + (size_t)R0 * 128 + col] =
                make_float2(hres[nt][0], hres[nt][1]);
            if (v1)
                *(float2*)&g_ht[hb + (size_t)R1 * 128 + col] =
                    make_float2(hres[nt][2], hres[nt][3]);
        }
    }
}

// ---------------------------------------------------------------------------
extern "C" void kernel_launch(void* const* d_in, const int* in_sizes, int n_in,
                              void* d_out, int out_size)
{
    const float* x     = (const float*)d_in[0];
    const float* dist  = (const float*)d_in[1];
    const float* w     = (const float*)d_in[2];
    const float* bias  = (const float*)d_in[3];
    const float* gamma = (const float*)d_in[4];
    const float* beta  = (const float*)d_in[5];
    float* out = (float*)d_out;

    cudaFuncSetAttribute(k_main, cudaFuncAttributeMaxDynamicSharedMemorySize,
                         SMEM_MAIN);

    int sms = 148;
    cudaDeviceGetAttribute(&sms, cudaDevAttrMultiProcessorCount, 0);

    dim3 tb(32, 8);
    dim3 tg(PD_ / 32, (T_ + 31) / 32, B_);

    k_tin<<<tg, tb>>>(x);
    k_main<<<sms, 256, SMEM_MAIN>>>(dist, w, bias, gamma, beta);
    k_tout<<<tg, tb>>>(out);
}

// round 7
// speedup vs baseline: 2.3384x; 1.1016x over previous
#include <cuda_runtime.h>
#include <cstdint>

#define B_  64
#define T_  120
#define P_  25
#define D_  128
#define PD_ 3200
#define NBT 7680
#define TILES 1536        // 5 bt per tile -> 125 rows padded to 128
#define ROWS_V 125
#define HS 132            // hy stride in floats (conflict-free A loads)
#define NT_ 512           // threads per CTA

// ---- smem byte offsets ----
#define SO_W   0                    // packed W fragments (float2): 2*16384*4 = 131072
#define SO_HY  131072               // 128*132*4 = 67584
#define SO_DS  198656               // 5*625*4 = 12500
#define SO_KN  211156               // 125*4*4 = 2000
#define SO_PS  213184               // 256*4
#define SO_PQ  214208               // 256*4
#define SO_BB  215232               // 256*4
#define SO_GG  216256               // 256*4
#define SO_BE  217280               // 256*4
#define SMEM_MAIN 218304

// scratch: h in [B*T, P*D] layout
__device__ float g_ht[(size_t)NBT * PD_];

static __device__ __forceinline__ uint32_t f2tf32(float x){
    uint32_t u; asm("cvt.rna.tf32.f32 %0, %1;" : "=r"(u) : "f"(x)); return u;
}
static __device__ __forceinline__ void mma8(float* c, uint32_t a0, uint32_t a1,
                                            uint32_t a2, uint32_t a3,
                                            uint32_t b0, uint32_t b1){
    asm volatile("mma.sync.aligned.m16n8k8.row.col.f32.tf32.tf32.f32 "
        "{%0,%1,%2,%3}, {%4,%5,%6,%7}, {%8,%9}, {%0,%1,%2,%3};"
        : "+f"(c[0]), "+f"(c[1]), "+f"(c[2]), "+f"(c[3])
        : "r"(a0), "r"(a1), "r"(a2), "r"(a3), "r"(b0), "r"(b1));
}

// ---------------------------------------------------------------------------
__global__ void k_tin(const float* __restrict__ x) {
    __shared__ float tile[32][33];
    const int b   = blockIdx.z;
    const int pd0 = blockIdx.x * 32;
    const int t0  = blockIdx.y * 32;
    const int tx = threadIdx.x, ty = threadIdx.y;
#pragma unroll
    for (int i = ty; i < 32; i += 8) {
        int t = t0 + tx;
        if (t < T_) tile[i][tx] = x[((size_t)b * PD_ + pd0 + i) * T_ + t];
    }
    __syncthreads();
#pragma unroll
    for (int i = ty; i < 32; i += 8) {
        int t = t0 + i;
        if (t < T_) g_ht[((size_t)b * T_ + t) * PD_ + pd0 + tx] = tile[tx][i];
    }
}

__global__ void k_tout(float* __restrict__ out) {
    __shared__ float tile[32][33];
    const int b   = blockIdx.z;
    const int pd0 = blockIdx.x * 32;
    const int t0  = blockIdx.y * 32;
    const int tx = threadIdx.x, ty = threadIdx.y;
#pragma unroll
    for (int i = ty; i < 32; i += 8) {
        int t = t0 + i;
        if (t < T_) tile[i][tx] = g_ht[((size_t)b * T_ + t) * PD_ + pd0 + tx];
    }
    __syncthreads();
#pragma unroll
    for (int i = ty; i < 32; i += 8) {
        int t = t0 + tx;
        if (t < T_) out[((size_t)b * PD_ + pd0 + i) * T_ + t] = tile[tx][i];
    }
}

// ---------------------------------------------------------------------------
// Main fused GCN: persistent CTAs, 5 bt/tile, 16 warps (rows x col-half split).
// ---------------------------------------------------------------------------
__global__ __launch_bounds__(NT_, 1)
void k_main(const float* __restrict__ dist_g,
            const float* __restrict__ w_g,
            const float* __restrict__ bias_g,
            const float* __restrict__ gamma_g,
            const float* __restrict__ beta_g)
{
    extern __shared__ char smc[];
    float* Ws = (float*)(smc + SO_W);
    float* hy = (float*)(smc + SO_HY);
    float* ds = (float*)(smc + SO_DS);
    int*   kn = (int*)  (smc + SO_KN);
    float* ps = (float*)(smc + SO_PS);
    float* pq = (float*)(smc + SO_PQ);
    float* bb = (float*)(smc + SO_BB);
    float* gg = (float*)(smc + SO_GG);
    float* be = (float*)(smc + SO_BE);

    const int tid  = threadIdx.x;
    const int warp = tid >> 5, lane = tid & 31;
    const int qr = lane >> 2;          // 0..7
    const int qc = lane & 3;           // 0..3
    const int m  = warp & 7;           // row-block
    const int cbh = warp >> 3;         // column half 0/1
    const int cb  = cbh * 64;
    const int R0 = m * 16 + qr;        // < 120, always valid
    const int R1 = R0 + 8;             // may be pad row
    const bool v1 = (R1 < ROWS_V);

    // ---- pack both weight matrices into fragment-order float2s ----
    // float2 idx = ((l*16+kt)*16+np16)*32 + qr*4 + qc :
    //   .x = W[8kt+qc][8*np16+qr], .y = W[8kt+qc+4][8*np16+qr]  (tf32-rounded)
    for (int i = tid; i < 2 * D_ * D_; i += NT_) {
        int l = i >> 14, k = (i >> 7) & 127, n = i & 127;
        int kt = k >> 3, c = k & 3, hi = (k >> 2) & 1;
        int np16 = n >> 3, g = n & 7;
        ((uint32_t*)Ws)[((((l*16 + kt)*16 + np16)*32 + g*4 + c) << 1) + hi] = f2tf32(w_g[i]);
    }
    if (tid < 256) {
        bb[tid] = bias_g[tid]; gg[tid] = gamma_g[tid]; be[tid] = beta_g[tid];
    }

    float hres[8][4];   // fp32 residual h, thread-owned (rows R0/R1, 16 cols)
    float acc[8][4];    // mma accumulators / z scratch

    for (int tile = blockIdx.x; tile < TILES; tile += gridDim.x) {
        // stage distances
        for (int i = tid; i < 5 * P_ * P_; i += NT_)
            ds[i] = dist_g[(size_t)tile * 3125 + i];

        const size_t hb = (size_t)tile * 16000;
        // stage h0 (tf32-rounded), zero pad rows
        for (int i = tid; i < 128 * 128; i += NT_) {
            int row = i >> 7, col = i & 127;
            float v = (row < ROWS_V) ? g_ht[hb + (size_t)row * 128 + col] : 0.f;
            ((uint32_t*)hy)[row * HS + col] = f2tf32(v);
        }
        // exact residual into registers
#pragma unroll
        for (int nt = 0; nt < 8; ++nt) {
            int col = cb + 8 * nt + 2 * qc;
            float2 a = *(const float2*)&g_ht[hb + (size_t)R0 * 128 + col];
            hres[nt][0] = a.x; hres[nt][1] = a.y;
            if (v1) {
                float2 b = *(const float2*)&g_ht[hb + (size_t)R1 * 128 + col];
                hres[nt][2] = b.x; hres[nt][3] = b.y;
            } else { hres[nt][2] = 0.f; hres[nt][3] = 0.f; }
        }
        __syncthreads();   // ds + hy staged (also guards prev-tile reuse)

        // kNN (4 smallest, self excluded); writes ordered by post-GEMM barrier
        if (tid < ROWS_V) {
            const int p = tid % 25;
            const float* dp = ds + (tid / 25) * 625 + p * 25;
            float bv0 = 1e30f, bv1 = 1e30f, bv2 = 1e30f, bv3 = 1e30f;
            int bi0 = 0, bi1 = 0, bi2 = 0, bi3 = 0;
            for (int q = 0; q < 25; ++q) {
                if (q == p) continue;
                float dv = dp[q];
                if (dv < bv3) {
                    bv3 = dv; bi3 = q;
                    if (bv3 < bv2) { float t=bv3; bv3=bv2; bv2=t; int ti=bi3; bi3=bi2; bi2=ti; }
                    if (bv2 < bv1) { float t=bv2; bv2=bv1; bv1=t; int ti=bi2; bi2=bi1; bi1=ti; }
                    if (bv1 < bv0) { float t=bv1; bv1=bv0; bv0=t; int ti=bi1; bi1=bi0; bi0=ti; }
                }
            }
            const int base = (tid / 25) * 25;
            kn[tid*4+0] = base + bi0; kn[tid*4+1] = base + bi1;
            kn[tid*4+2] = base + bi2; kn[tid*4+3] = base + bi3;
        }

#pragma unroll
        for (int l = 0; l < 2; ++l) {
            // ---- y = h @ W_l  (warp: 16 rows x 64 cols) ----
#pragma unroll
            for (int nt = 0; nt < 8; ++nt)
#pragma unroll
                for (int j = 0; j < 4; ++j) acc[nt][j] = 0.f;

            const uint32_t* hyu = (const uint32_t*)hy;
            const float2* wf = (const float2*)Ws
                + (size_t)l*16*16*32 + cbh*8*32 + qr*4 + qc;
#pragma unroll
            for (int kt = 0; kt < 16; ++kt) {
                uint32_t a0 = hyu[R0 * HS + 8*kt + qc];
                uint32_t a1 = hyu[R1 * HS + 8*kt + qc];
                uint32_t a2 = hyu[R0 * HS + 8*kt + qc + 4];
                uint32_t a3 = hyu[R1 * HS + 8*kt + qc + 4];
                const float2* wk = wf + kt*16*32;
#pragma unroll
                for (int np = 0; np < 8; ++np) {
                    float2 b = wk[np*32];
                    mma8(acc[np], a0, a1, a2, a3,
                         __float_as_uint(b.x), __float_as_uint(b.y));
                }
            }
            __syncthreads();   // all A reads done; hy becomes y buffer

            // stage y into hy
#pragma unroll
            for (int nt = 0; nt < 8; ++nt) {
                int col = cb + 8*nt + 2*qc;
                *(float2*)&hy[R0 * HS + col] = make_float2(acc[nt][0], acc[nt][1]);
                *(float2*)&hy[R1 * HS + col] = make_float2(acc[nt][2], acc[nt][3]);
            }
            __syncthreads();

            // gather (self + 4 nb)/5 + bias + relu; partial LN stats
            const int kb0 = R0 * 4;
            const int kb1 = (v1 ? R1 : 0) * 4;
            const int n00 = kn[kb0+0], n01 = kn[kb0+1], n02 = kn[kb0+2], n03 = kn[kb0+3];
            const int n10 = kn[kb1+0], n11 = kn[kb1+1], n12 = kn[kb1+2], n13 = kn[kb1+3];
            float S0 = 0.f, Q0 = 0.f, S1 = 0.f, Q1 = 0.f;
#pragma unroll
            for (int nt = 0; nt < 8; ++nt) {
                int col = cb + 8*nt + 2*qc;
                float2 bi2v = *(const float2*)&bb[l*128 + col];
                float2 e0 = *(const float2*)&hy[n00*HS + col];
                float2 e1 = *(const float2*)&hy[n01*HS + col];
                float2 e2 = *(const float2*)&hy[n02*HS + col];
                float2 e3 = *(const float2*)&hy[n03*HS + col];
                float z0 = fmaxf(fmaf(0.2f, acc[nt][0]+e0.x+e1.x+e2.x+e3.x, bi2v.x), 0.f);
                float z1 = fmaxf(fmaf(0.2f, acc[nt][1]+e0.y+e1.y+e2.y+e3.y, bi2v.y), 0.f);
                float2 f0 = *(const float2*)&hy[n10*HS + col];
                float2 f1 = *(const float2*)&hy[n11*HS + col];
                float2 f2 = *(const float2*)&hy[n12*HS + col];
                float2 f3 = *(const float2*)&hy[n13*HS + col];
                float z2 = fmaxf(fmaf(0.2f, acc[nt][2]+f0.x+f1.x+f2.x+f3.x, bi2v.x), 0.f);
                float z3 = fmaxf(fmaf(0.2f, acc[nt][3]+f0.y+f1.y+f2.y+f3.y, bi2v.y), 0.f);
                acc[nt][0] = z0; acc[nt][1] = z1; acc[nt][2] = z2; acc[nt][3] = z3;
                S0 += z0 + z1; Q0 = fmaf(z0, z0, Q0); Q0 = fmaf(z1, z1, Q0);
                S1 += z2 + z3; Q1 = fmaf(z2, z2, Q1); Q1 = fmaf(z3, z3, Q1);
            }
            // quad-reduce -> 64-col partials; exchange halves via smem
            S0 += __shfl_xor_sync(0xffffffffu, S0, 1); S0 += __shfl_xor_sync(0xffffffffu, S0, 2);
            Q0 += __shfl_xor_sync(0xffffffffu, Q0, 1); Q0 += __shfl_xor_sync(0xffffffffu, Q0, 2);
            S1 += __shfl_xor_sync(0xffffffffu, S1, 1); S1 += __shfl_xor_sync(0xffffffffu, S1, 2);
            Q1 += __shfl_xor_sync(0xffffffffu, Q1, 1); Q1 += __shfl_xor_sync(0xffffffffu, Q1, 2);
            if (qc == 0) {
                ps[cbh*128 + R0] = S0; pq[cbh*128 + R0] = Q0;
                ps[cbh*128 + R1] = S1; pq[cbh*128 + R1] = Q1;
            }
            __syncthreads();   // partials visible; all gather reads done
            float Sa = ps[R0] + ps[128 + R0];
            float Qa = pq[R0] + pq[128 + R0];
            float Sb = ps[R1] + ps[128 + R1];
            float Qb = pq[R1] + pq[128 + R1];
            float mu0 = Sa * (1.f/128.f), var0 = Qa * (1.f/128.f) - mu0*mu0;
            float mu1 = Sb * (1.f/128.f), var1 = Qb * (1.f/128.f) - mu1*mu1;
            float rs0 = rsqrtf(var0 + 1e-5f), rs1 = rsqrtf(var1 + 1e-5f);
#pragma unroll
            for (int nt = 0; nt < 8; ++nt) {
                int col = cb + 8*nt + 2*qc;
                float2 g2 = *(const float2*)&gg[l*128 + col];
                float2 b2 = *(const float2*)&be[l*128 + col];
                hres[nt][0] += (acc[nt][0] - mu0) * rs0 * g2.x + b2.x;
                hres[nt][1] += (acc[nt][1] - mu0) * rs0 * g2.y + b2.y;
                hres[nt][2] += (acc[nt][2] - mu1) * rs1 * g2.x + b2.x;
                hres[nt][3] += (acc[nt][3] - mu1) * rs1 * g2.y + b2.y;
            }

            if (l == 0) {
                // store h1 (tf32) as next layer's A; keep pad rows zero
#pragma unroll
                for (int nt = 0; nt < 8; ++nt) {
                    int col = cb + 8*nt + 2*qc;
                    ((uint32_t*)hy)[R0*HS + col]     = f2tf32(hres[nt][0]);
                    ((uint32_t*)hy)[R0*HS + col + 1] = f2tf32(hres[nt][1]);
                    ((uint32_t*)hy)[R1*HS + col]     = v1 ? f2tf32(hres[nt][2]) : 0u;
                    ((uint32_t*)hy)[R1*HS + col + 1] = v1 ? f2tf32(hres[nt][3]) : 0u;
                }
                __syncthreads();   // h1 complete before next-layer GEMM
            }
        }

        // write back final h (exact, from registers)
#pragma unroll
        for (int nt = 0; nt < 8; ++nt) {
            int col = cb + 8*nt + 2*qc;
            *(float2*)&g_ht[hb + (size_t)R0 * 128 + col] =
                make_float2(hres[nt][0], hres[nt][1]);
            if (v1)
                *(float2*)&g_ht[hb + (size_t)R1 * 128 + col] =
                    make_float2(hres[nt][2], hres[nt][3]);
        }
        __syncthreads();   // writeback/gather done before next tile restage
    }
}

// ---------------------------------------------------------------------------
extern "C" void kernel_launch(void* const* d_in, const int* in_sizes, int n_in,
                              void* d_out, int out_size)
{
    const float* x     = (const float*)d_in[0];
    const float* dist  = (const float*)d_in[1];
    const float* w     = (const float*)d_in[2];
    const float* bias  = (const float*)d_in[3];
    const float* gamma = (const float*)d_in[4];
    const float* beta  = (const float*)d_in[5];
    float* out = (float*)d_out;

    cudaFuncSetAttribute(k_main, cudaFuncAttributeMaxDynamicSharedMemorySize,
                         SMEM_MAIN);

    int sms = 148;
    cudaDeviceGetAttribute(&sms, cudaDevAttrMultiProcessorCount, 0);

    dim3 tb(32, 8);
    dim3 tg(PD_ / 32, (T_ + 31) / 32, B_);

    k_tin<<<tg, tb>>>(x);
    k_main<<<sms, NT_, SMEM_MAIN>>>(dist, w, bias, gamma, beta);
    k_tout<<<tg, tb>>>(out);
}

// round 8
// speedup vs baseline: 2.5494x; 1.0903x over previous
#include <cuda_runtime.h>
#include <cstdint>

#define B_  64
#define T_  120
#define P_  25
#define D_  128
#define TILES 1536        // (b, 5-t group); 125 rows padded to 128
#define ROWS_V 125
#define HS 132            // hy stride in floats (conflict-free A loads)
#define NT_ 512           // threads per CTA
#define XSTR 384000       // per-b stride in x/out (3200*120)

// ---- smem byte offsets ----
#define SO_W   0                    // packed W fragments (float4): 131072
#define SO_HY  131072               // 128*132*4 = 67584
#define SO_DS  198656               // 5*625*4 = 12500
#define SO_KN  211156               // 125*4*4 = 2000
#define SO_PS  213184               // 256*4
#define SO_PQ  214208               // 256*4
#define SO_BB  215232               // 256*4
#define SO_GG  216256               // 256*4
#define SO_BE  217280               // 256*4
#define SMEM_MAIN 218304

static __device__ __forceinline__ uint32_t f2tf32(float x){
    uint32_t u; asm("cvt.rna.tf32.f32 %0, %1;" : "=r"(u) : "f"(x)); return u;
}
static __device__ __forceinline__ void mma8(float* c, uint32_t a0, uint32_t a1,
                                            uint32_t a2, uint32_t a3,
                                            uint32_t b0, uint32_t b1){
    asm volatile("mma.sync.aligned.m16n8k8.row.col.f32.tf32.tf32.f32 "
        "{%0,%1,%2,%3}, {%4,%5,%6,%7}, {%8,%9}, {%0,%1,%2,%3};"
        : "+f"(c[0]), "+f"(c[1]), "+f"(c[2]), "+f"(c[3])
        : "r"(a0), "r"(a1), "r"(a2), "r"(a3), "r"(b0), "r"(b1));
}

// ---------------------------------------------------------------------------
// Single fused kernel: in-tile transpose-in, GCN x2, transpose-out.
// ---------------------------------------------------------------------------
__global__ __launch_bounds__(NT_, 1)
void k_main(const float* __restrict__ x,
            const float* __restrict__ dist_g,
            const float* __restrict__ w_g,
            const float* __restrict__ bias_g,
            const float* __restrict__ gamma_g,
            const float* __restrict__ beta_g,
            float* __restrict__ out)
{
    extern __shared__ char smc[];
    float* Ws = (float*)(smc + SO_W);
    float* hy = (float*)(smc + SO_HY);
    float* ds = (float*)(smc + SO_DS);
    int*   kn = (int*)  (smc + SO_KN);
    float* ps = (float*)(smc + SO_PS);
    float* pq = (float*)(smc + SO_PQ);
    float* bb = (float*)(smc + SO_BB);
    float* gg = (float*)(smc + SO_GG);
    float* be = (float*)(smc + SO_BE);

    const int tid  = threadIdx.x;
    const int warp = tid >> 5, lane = tid & 31;
    const int qr = lane >> 2;          // 0..7
    const int qc = lane & 3;           // 0..3
    const int m  = warp & 7;           // row-block
    const int cbh = warp >> 3;         // column half 0/1
    const int cb  = cbh * 64;
    const int R0 = m * 16 + qr;        // < 120, always valid
    const int R1 = R0 + 8;             // may be pad row
    const bool v1 = (R1 < ROWS_V);

    // ---- pack both weight matrices into fragment-order float4s ----
    // float4 group idx = ((l*16+kt)*8 + nh*4 + j)*32 + qr*4 + c, components:
    //   x = W[8kt+c][8*(8nh+2j)+qr],   y = W[8kt+c+4][8*(8nh+2j)+qr],
    //   z = W[8kt+c][8*(8nh+2j+1)+qr], w = W[8kt+c+4][8*(8nh+2j+1)+qr]
    for (int i = tid; i < 2 * D_ * D_; i += NT_) {
        int l = i >> 14, k = (i >> 7) & 127, n = i & 127;
        int kt = k >> 3, c = k & 3, hi = (k >> 2) & 1;
        int g = n & 7, np = n >> 3;
        int nh = np >> 3, j = (np >> 1) & 3, od = np & 1;
        ((uint32_t*)Ws)[(((((l*16 + kt)*8 + nh*4 + j)*32 + g*4 + c) << 2)
                         + ((od << 1) | hi))] = f2tf32(w_g[i]);
    }
    if (tid < 256) {
        bb[tid] = bias_g[tid]; gg[tid] = gamma_g[tid]; be[tid] = beta_g[tid];
    }
    __syncthreads();

    float hres[8][4];   // fp32 residual h, thread-owned (rows R0/R1, 16 cols)
    float acc[8][4];    // mma accumulators / z scratch

    for (int tile = blockIdx.x; tile < TILES; tile += gridDim.x) {
        const int b  = tile / 24;
        const int t0 = (tile - b * 24) * 5;
        const float* xb = x + (size_t)b * XSTR + t0;
        float* ob = out + (size_t)b * XSTR + t0;

        // ---- stage x -> hy (fp32), (pd, t)-ordered for 20B gmem chunks ----
        for (int i = tid; i < 16000; i += NT_) {
            int pd = i / 5, tl = i - pd * 5;
            int p = pd >> 7, col = pd & 127;
            hy[(tl * 25 + p) * HS + col] = xb[(size_t)pd * 120 + tl];
        }
        // stage distances (contiguous for 5 consecutive t)
        for (int i = tid; i < 5 * P_ * P_; i += NT_)
            ds[i] = dist_g[(size_t)tile * 3125 + i];
        __syncthreads();

        // ---- exact residual from hy + in-place tf32 convert (exact ownership,
        //      pad rows forced to zero) ----
#pragma unroll
        for (int nt = 0; nt < 8; ++nt) {
            int col = cb + 8 * nt + 2 * qc;
            float2 a = *(const float2*)&hy[R0 * HS + col];
            hres[nt][0] = a.x; hres[nt][1] = a.y;
            *(uint2*)&((uint32_t*)hy)[R0 * HS + col] =
                make_uint2(f2tf32(a.x), f2tf32(a.y));
            if (v1) {
                float2 bv = *(const float2*)&hy[R1 * HS + col];
                hres[nt][2] = bv.x; hres[nt][3] = bv.y;
                *(uint2*)&((uint32_t*)hy)[R1 * HS + col] =
                    make_uint2(f2tf32(bv.x), f2tf32(bv.y));
            } else {
                hres[nt][2] = 0.f; hres[nt][3] = 0.f;
                *(uint2*)&((uint32_t*)hy)[R1 * HS + col] = make_uint2(0u, 0u);
            }
        }

        // kNN (4 smallest, self excluded); kn read after next barrier
        if (tid < ROWS_V) {
            const int p = tid % 25;
            const float* dp = ds + (tid / 25) * 625 + p * 25;
            float bv0 = 1e30f, bv1 = 1e30f, bv2 = 1e30f, bv3 = 1e30f;
            int bi0 = 0, bi1 = 0, bi2 = 0, bi3 = 0;
            for (int q = 0; q < 25; ++q) {
                if (q == p) continue;
                float dv = dp[q];
                if (dv < bv3) {
                    bv3 = dv; bi3 = q;
                    if (bv3 < bv2) { float t=bv3; bv3=bv2; bv2=t; int ti=bi3; bi3=bi2; bi2=ti; }
                    if (bv2 < bv1) { float t=bv2; bv2=bv1; bv1=t; int ti=bi2; bi2=bi1; bi1=ti; }
                    if (bv1 < bv0) { float t=bv1; bv1=bv0; bv0=t; int ti=bi1; bi1=bi0; bi0=ti; }
                }
            }
            const int base = (tid / 25) * 25;
            kn[tid*4+0] = base + bi0; kn[tid*4+1] = base + bi1;
            kn[tid*4+2] = base + bi2; kn[tid*4+3] = base + bi3;
        }
        __syncthreads();   // hy fully tf32 + kn ready

#pragma unroll
        for (int l = 0; l < 2; ++l) {
            // ---- y = h @ W_l  (warp: 16 rows x 64 cols) ----
#pragma unroll
            for (int nt = 0; nt < 8; ++nt)
#pragma unroll
                for (int j = 0; j < 4; ++j) acc[nt][j] = 0.f;

            const uint32_t* hyu = (const uint32_t*)hy;
            const float4* wf = (const float4*)Ws
                + (size_t)l*16*8*32 + cbh*4*32 + qr*4 + qc;
#pragma unroll
            for (int kt = 0; kt < 16; ++kt) {
                uint32_t a0 = hyu[R0 * HS + 8*kt + qc];
                uint32_t a1 = hyu[R1 * HS + 8*kt + qc];
                uint32_t a2 = hyu[R0 * HS + 8*kt + qc + 4];
                uint32_t a3 = hyu[R1 * HS + 8*kt + qc + 4];
                const float4* wk = wf + kt*8*32;
#pragma unroll
                for (int j = 0; j < 4; ++j) {
                    float4 bv = wk[j*32];
                    mma8(acc[2*j],     a0, a1, a2, a3,
                         __float_as_uint(bv.x), __float_as_uint(bv.y));
                    mma8(acc[2*j + 1], a0, a1, a2, a3,
                         __float_as_uint(bv.z), __float_as_uint(bv.w));
                }
            }
            __syncthreads();   // all A reads done; hy becomes y buffer

            // stage y into hy
#pragma unroll
            for (int nt = 0; nt < 8; ++nt) {
                int col = cb + 8*nt + 2*qc;
                *(float2*)&hy[R0 * HS + col] = make_float2(acc[nt][0], acc[nt][1]);
                *(float2*)&hy[R1 * HS + col] = make_float2(acc[nt][2], acc[nt][3]);
            }
            __syncthreads();

            // gather (self + 4 nb)/5 + bias + relu; partial LN stats
            const int kb0 = R0 * 4;
            const int kb1 = (v1 ? R1 : 0) * 4;
            const int n00 = kn[kb0+0], n01 = kn[kb0+1], n02 = kn[kb0+2], n03 = kn[kb0+3];
            const int n10 = kn[kb1+0], n11 = kn[kb1+1], n12 = kn[kb1+2], n13 = kn[kb1+3];
            float S0 = 0.f, Q0 = 0.f, S1 = 0.f, Q1 = 0.f;
#pragma unroll
            for (int nt = 0; nt < 8; ++nt) {
                int col = cb + 8*nt + 2*qc;
                float2 bi2v = *(const float2*)&bb[l*128 + col];
                float2 e0 = *(const float2*)&hy[n00*HS + col];
                float2 e1 = *(const float2*)&hy[n01*HS + col];
                float2 e2 = *(const float2*)&hy[n02*HS + col];
                float2 e3 = *(const float2*)&hy[n03*HS + col];
                float z0 = fmaxf(fmaf(0.2f, acc[nt][0]+e0.x+e1.x+e2.x+e3.x, bi2v.x), 0.f);
                float z1 = fmaxf(fmaf(0.2f, acc[nt][1]+e0.y+e1.y+e2.y+e3.y, bi2v.y), 0.f);
                float2 f0 = *(const float2*)&hy[n10*HS + col];
                float2 f1 = *(const float2*)&hy[n11*HS + col];
                float2 f2 = *(const float2*)&hy[n12*HS + col];
                float2 f3 = *(const float2*)&hy[n13*HS + col];
                float z2 = fmaxf(fmaf(0.2f, acc[nt][2]+f0.x+f1.x+f2.x+f3.x, bi2v.x), 0.f);
                float z3 = fmaxf(fmaf(0.2f, acc[nt][3]+f0.y+f1.y+f2.y+f3.y, bi2v.y), 0.f);
                acc[nt][0] = z0; acc[nt][1] = z1; acc[nt][2] = z2; acc[nt][3] = z3;
                S0 += z0 + z1; Q0 = fmaf(z0, z0, Q0); Q0 = fmaf(z1, z1, Q0);
                S1 += z2 + z3; Q1 = fmaf(z2, z2, Q1); Q1 = fmaf(z3, z3, Q1);
            }
            // quad-reduce -> 64-col partials; exchange halves via smem
            S0 += __shfl_xor_sync(0xffffffffu, S0, 1); S0 += __shfl_xor_sync(0xffffffffu, S0, 2);
            Q0 += __shfl_xor_sync(0xffffffffu, Q0, 1); Q0 += __shfl_xor_sync(0xffffffffu, Q0, 2);
            S1 += __shfl_xor_sync(0xffffffffu, S1, 1); S1 += __shfl_xor_sync(0xffffffffu, S1, 2);
            Q1 += __shfl_xor_sync(0xffffffffu, Q1, 1); Q1 += __shfl_xor_sync(0xffffffffu, Q1, 2);
            if (qc == 0) {
                ps[cbh*128 + R0] = S0; pq[cbh*128 + R0] = Q0;
                ps[cbh*128 + R1] = S1; pq[cbh*128 + R1] = Q1;
            }
            __syncthreads();   // partials visible; all gather reads done
            float Sa = ps[R0] + ps[128 + R0];
            float Qa = pq[R0] + pq[128 + R0];
            float Sb = ps[R1] + ps[128 + R1];
            float Qb = pq[R1] + pq[128 + R1];
            float mu0 = Sa * (1.f/128.f), var0 = Qa * (1.f/128.f) - mu0*mu0;
            float mu1 = Sb * (1.f/128.f), var1 = Qb * (1.f/128.f) - mu1*mu1;
            float rs0 = rsqrtf(var0 + 1e-5f), rs1 = rsqrtf(var1 + 1e-5f);
#pragma unroll
            for (int nt = 0; nt < 8; ++nt) {
                int col = cb + 8*nt + 2*qc;
                float2 g2 = *(const float2*)&gg[l*128 + col];
                float2 b2 = *(const float2*)&be[l*128 + col];
                hres[nt][0] += (acc[nt][0] - mu0) * rs0 * g2.x + b2.x;
                hres[nt][1] += (acc[nt][1] - mu0) * rs0 * g2.y + b2.y;
                hres[nt][2] += (acc[nt][2] - mu1) * rs1 * g2.x + b2.x;
                hres[nt][3] += (acc[nt][3] - mu1) * rs1 * g2.y + b2.y;
            }

            if (l == 0) {
                // store h1 (tf32) as next layer's A; keep pad rows zero
#pragma unroll
                for (int nt = 0; nt < 8; ++nt) {
                    int col = cb + 8*nt + 2*qc;
                    *(uint2*)&((uint32_t*)hy)[R0*HS + col] =
                        make_uint2(f2tf32(hres[nt][0]), f2tf32(hres[nt][1]));
                    *(uint2*)&((uint32_t*)hy)[R1*HS + col] = v1
                        ? make_uint2(f2tf32(hres[nt][2]), f2tf32(hres[nt][3]))
                        : make_uint2(0u, 0u);
                }
                __syncthreads();   // h1 complete before next-layer GEMM
            } else {
                // stage final h (fp32) into hy for transposed writeback
#pragma unroll
                for (int nt = 0; nt < 8; ++nt) {
                    int col = cb + 8*nt + 2*qc;
                    *(float2*)&hy[R0*HS + col] = make_float2(hres[nt][0], hres[nt][1]);
                    if (v1)
                        *(float2*)&hy[R1*HS + col] = make_float2(hres[nt][2], hres[nt][3]);
                }
                __syncthreads();
            }
        }

        // ---- writeback: hy -> out, (pd, t)-ordered for 20B gmem chunks ----
        for (int i = tid; i < 16000; i += NT_) {
            int pd = i / 5, tl = i - pd * 5;
            int p = pd >> 7, col = pd & 127;
            ob[(size_t)pd * 120 + tl] = hy[(tl * 25 + p) * HS + col];
        }
        __syncthreads();   // out reads done before next tile restages hy
    }
}

// ---------------------------------------------------------------------------
extern "C" void kernel_launch(void* const* d_in, const int* in_sizes, int n_in,
                              void* d_out, int out_size)
{
    const float* x     = (const float*)d_in[0];
    const float* dist  = (const float*)d_in[1];
    const float* w     = (const float*)d_in[2];
    const float* bias  = (const float*)d_in[3];
    const float* gamma = (const float*)d_in[4];
    const float* beta  = (const float*)d_in[5];
    float* out = (float*)d_out;

    cudaFuncSetAttribute(k_main, cudaFuncAttributeMaxDynamicSharedMemorySize,
                         SMEM_MAIN);

    int sms = 148;
    cudaDeviceGetAttribute(&sms, cudaDevAttrMultiProcessorCount, 0);

    k_main<<<sms, NT_, SMEM_MAIN>>>(x, dist, w, bias, gamma, beta, out);
}

// round 10
// speedup vs baseline: 2.6045x; 1.0216x over previous
#include <cuda_runtime.h>
#include <cstdint>

#define B_  64
#define T_  120
#define P_  25
#define D_  128
#define TILES 1536        // (b, 5-t group); 125 rows padded to 128
#define ROWS_V 125
#define HS 132            // hy stride in floats (conflict-free A loads)
#define NT_ 1024          // threads per CTA (32 warps)
#define XSTR 384000       // per-b stride in x/out (3200*120)

// ---- smem byte offsets ----
#define SO_W   0                    // packed W fragments (float4): 131072
#define SO_HY  131072               // 128*132*4 = 67584
#define SO_DS  198656               // 5*625*4 = 12500
#define SO_KN  211156               // 125*4*4 = 2000
#define SO_PS  213184               // 512*4 = 2048
#define SO_PQ  215232               // 512*4 = 2048
#define SO_BB  217280               // 256*4
#define SO_GG  218304               // 256*4
#define SO_BE  219328               // 256*4
#define SMEM_MAIN 220352

static __device__ __forceinline__ uint32_t f2tf32(float x){
    uint32_t u; asm("cvt.rna.tf32.f32 %0, %1;" : "=r"(u) : "f"(x)); return u;
}
static __device__ __forceinline__ void mma8(float* c, uint32_t a0, uint32_t a1,
                                            uint32_t a2, uint32_t a3,
                                            uint32_t b0, uint32_t b1){
    asm volatile("mma.sync.aligned.m16n8k8.row.col.f32.tf32.tf32.f32 "
        "{%0,%1,%2,%3}, {%4,%5,%6,%7}, {%8,%9}, {%0,%1,%2,%3};"
        : "+f"(c[0]), "+f"(c[1]), "+f"(c[2]), "+f"(c[3])
        : "r"(a0), "r"(a1), "r"(a2), "r"(a3), "r"(b0), "r"(b1));
}

// ---------------------------------------------------------------------------
// Single fused kernel: in-tile transpose-in, GCN x2, transpose-out.
// 32 warps: 8 row-blocks (16 rows) x 4 col-quarters (32 cols).
// ---------------------------------------------------------------------------
__global__ __launch_bounds__(NT_, 1)
void k_main(const float* __restrict__ x,
            const float* __restrict__ dist_g,
            const float* __restrict__ w_g,
            const float* __restrict__ bias_g,
            const float* __restrict__ gamma_g,
            const float* __restrict__ beta_g,
            float* __restrict__ out)
{
    extern __shared__ char smc[];
    float* Ws = (float*)(smc + SO_W);
    float* hy = (float*)(smc + SO_HY);
    float* ds = (float*)(smc + SO_DS);
    int*   kn = (int*)  (smc + SO_KN);
    float* ps = (float*)(smc + SO_PS);
    float* pq = (float*)(smc + SO_PQ);
    float* bb = (float*)(smc + SO_BB);
    float* gg = (float*)(smc + SO_GG);
    float* be = (float*)(smc + SO_BE);

    const int tid  = threadIdx.x;
    const int warp = tid >> 5, lane = tid & 31;
    const int qr = lane >> 2;          // 0..7
    const int qc = lane & 3;           // 0..3
    const int m  = warp & 7;           // row-block
    const int cq = warp >> 3;          // col quarter 0..3
    const int cb = cq * 32;
    const int R0 = m * 16 + qr;        // < 120, always valid
    const int R1 = R0 + 8;             // may be pad row
    const bool v1 = (R1 < ROWS_V);

    // ---- pack both weight matrices into fragment-order float4s ----
    // float4 idx = ((l*16+kt)*8 + cq*2 + j)*32 + qr*4 + c, components:
    //   x = W[8kt+c][8*(8cq+2j)+qr],   y = W[8kt+c+4][8*(8cq+2j)+qr],
    //   z = W[8kt+c][8*(8cq+2j+1)+qr], w = W[8kt+c+4][8*(8cq+2j+1)+qr]
    for (int i = tid; i < 2 * D_ * D_; i += NT_) {
        int l = i >> 14, k = (i >> 7) & 127, n = i & 127;
        int kt = k >> 3, c = k & 3, hi = (k >> 2) & 1;
        int g = n & 7, np8 = n >> 3;
        int q4 = np8 >> 2, j = (np8 >> 1) & 1, od = np8 & 1;
        ((uint32_t*)Ws)[(((((l*16 + kt)*8 + q4*2 + j)*32 + g*4 + c) << 2)
                         + ((od << 1) | hi))] = f2tf32(w_g[i]);
    }
    if (tid < 256) {
        bb[tid] = bias_g[tid]; gg[tid] = gamma_g[tid]; be[tid] = beta_g[tid];
    }
    __syncthreads();

    float hres[4][4];   // fp32 residual h (rows R0/R1, 8 owned cols)
    float acc[4][4];    // mma accumulators / z scratch

    for (int tile = blockIdx.x; tile < TILES; tile += gridDim.x) {
        const int b  = tile / 24;
        const int t0 = (tile - b * 24) * 5;
        const float* xb = x + (size_t)b * XSTR + t0;
        float* ob = out + (size_t)b * XSTR + t0;

        // ---- stage x -> hy (fp32), (pd, t)-ordered for 20B gmem chunks ----
        for (int i = tid; i < 16000; i += NT_) {
            int pd = i / 5, tl = i - pd * 5;
            int p = pd >> 7, col = pd & 127;
            hy[(tl * 25 + p) * HS + col] = xb[(size_t)pd * 120 + tl];
        }
        // stage distances (contiguous for 5 consecutive t)
        for (int i = tid; i < 5 * P_ * P_; i += NT_)
            ds[i] = dist_g[(size_t)tile * 3125 + i];
        __syncthreads();

        // ---- exact residual from hy + in-place tf32 convert (exact ownership,
        //      pad rows forced to zero) ----
#pragma unroll
        for (int nt = 0; nt < 4; ++nt) {
            int col = cb + 8 * nt + 2 * qc;
            float2 a = *(const float2*)&hy[R0 * HS + col];
            hres[nt][0] = a.x; hres[nt][1] = a.y;
            *(uint2*)&((uint32_t*)hy)[R0 * HS + col] =
                make_uint2(f2tf32(a.x), f2tf32(a.y));
            if (v1) {
                float2 bv = *(const float2*)&hy[R1 * HS + col];
                hres[nt][2] = bv.x; hres[nt][3] = bv.y;
                *(uint2*)&((uint32_t*)hy)[R1 * HS + col] =
                    make_uint2(f2tf32(bv.x), f2tf32(bv.y));
            } else {
                hres[nt][2] = 0.f; hres[nt][3] = 0.f;
                *(uint2*)&((uint32_t*)hy)[R1 * HS + col] = make_uint2(0u, 0u);
            }
        }

        // kNN (4 smallest, self excluded); kn read after next barrier
        if (tid < ROWS_V) {
            const int p = tid % 25;
            const float* dp = ds + (tid / 25) * 625 + p * 25;
            float bv0 = 1e30f, bv1 = 1e30f, bv2 = 1e30f, bv3 = 1e30f;
            int bi0 = 0, bi1 = 0, bi2 = 0, bi3 = 0;
            for (int q = 0; q < 25; ++q) {
                if (q == p) continue;
                float dv = dp[q];
                if (dv < bv3) {
                    bv3 = dv; bi3 = q;
                    if (bv3 < bv2) { float t=bv3; bv3=bv2; bv2=t; int ti=bi3; bi3=bi2; bi2=ti; }
                    if (bv2 < bv1) { float t=bv2; bv2=bv1; bv1=t; int ti=bi2; bi2=bi1; bi1=ti; }
                    if (bv1 < bv0) { float t=bv1; bv1=bv0; bv0=t; int ti=bi1; bi1=bi0; bi0=ti; }
                }
            }
            const int base = (tid / 25) * 25;
            kn[tid*4+0] = base + bi0; kn[tid*4+1] = base + bi1;
            kn[tid*4+2] = base + bi2; kn[tid*4+3] = base + bi3;
        }
        __syncthreads();   // hy fully tf32 + kn ready

#pragma unroll
        for (int l = 0; l < 2; ++l) {
            // ---- y = h @ W_l  (warp: 16 rows x 32 cols) ----
#pragma unroll
            for (int nt = 0; nt < 4; ++nt)
#pragma unroll
                for (int j = 0; j < 4; ++j) acc[nt][j] = 0.f;

            const uint32_t* hyu = (const uint32_t*)hy;
            const float4* wf = (const float4*)Ws
                + (size_t)l*16*8*32 + cq*2*32 + qr*4 + qc;
#pragma unroll
            for (int kt = 0; kt < 16; ++kt) {
                uint32_t a0 = hyu[R0 * HS + 8*kt + qc];
                uint32_t a1 = hyu[R1 * HS + 8*kt + qc];
                uint32_t a2 = hyu[R0 * HS + 8*kt + qc + 4];
                uint32_t a3 = hyu[R1 * HS + 8*kt + qc + 4];
                const float4* wk = wf + kt*8*32;
#pragma unroll
                for (int j = 0; j < 2; ++j) {
                    float4 bv = wk[j*32];
                    mma8(acc[2*j],     a0, a1, a2, a3,
                         __float_as_uint(bv.x), __float_as_uint(bv.y));
                    mma8(acc[2*j + 1], a0, a1, a2, a3,
                         __float_as_uint(bv.z), __float_as_uint(bv.w));
                }
            }
            __syncthreads();   // all A reads done; hy becomes y buffer

            // stage y into hy
#pragma unroll
            for (int nt = 0; nt < 4; ++nt) {
                int col = cb + 8*nt + 2*qc;
                *(float2*)&hy[R0 * HS + col] = make_float2(acc[nt][0], acc[nt][1]);
                *(float2*)&hy[R1 * HS + col] = make_float2(acc[nt][2], acc[nt][3]);
            }
            __syncthreads();

            // gather (self + 4 nb)/5 + bias + relu; partial LN stats
            const int kb0 = R0 * 4;
            const int kb1 = (v1 ? R1 : 0) * 4;
            const int n00 = kn[kb0+0], n01 = kn[kb0+1], n02 = kn[kb0+2], n03 = kn[kb0+3];
            const int n10 = kn[kb1+0], n11 = kn[kb1+1], n12 = kn[kb1+2], n13 = kn[kb1+3];
            float S0 = 0.f, Q0 = 0.f, S1 = 0.f, Q1 = 0.f;
#pragma unroll
            for (int nt = 0; nt < 4; ++nt) {
                int col = cb + 8*nt + 2*qc;
                float2 bi2v = *(const float2*)&bb[l*128 + col];
                float2 e0 = *(const float2*)&hy[n00*HS + col];
                float2 e1 = *(const float2*)&hy[n01*HS + col];
                float2 e2 = *(const float2*)&hy[n02*HS + col];
                float2 e3 = *(const float2*)&hy[n03*HS + col];
                float z0 = fmaxf(fmaf(0.2f, acc[nt][0]+e0.x+e1.x+e2.x+e3.x, bi2v.x), 0.f);
                float z1 = fmaxf(fmaf(0.2f, acc[nt][1]+e0.y+e1.y+e2.y+e3.y, bi2v.y), 0.f);
                float2 f0 = *(const float2*)&hy[n10*HS + col];
                float2 f1 = *(const float2*)&hy[n11*HS + col];
                float2 f2 = *(const float2*)&hy[n12*HS + col];
                float2 f3 = *(const float2*)&hy[n13*HS + col];
                float z2 = fmaxf(fmaf(0.2f, acc[nt][2]+f0.x+f1.x+f2.x+f3.x, bi2v.x), 0.f);
                float z3 = fmaxf(fmaf(0.2f, acc[nt][3]+f0.y+f1.y+f2.y+f3.y, bi2v.y), 0.f);
                acc[nt][0] = z0; acc[nt][1] = z1; acc[nt][2] = z2; acc[nt][3] = z3;
                S0 += z0 + z1; Q0 = fmaf(z0, z0, Q0); Q0 = fmaf(z1, z1, Q0);
                S1 += z2 + z3; Q1 = fmaf(z2, z2, Q1); Q1 = fmaf(z3, z3, Q1);
            }
            // quad-reduce -> 32-col partials; combine 4 quarters via smem
            S0 += __shfl_xor_sync(0xffffffffu, S0, 1); S0 += __shfl_xor_sync(0xffffffffu, S0, 2);
            Q0 += __shfl_xor_sync(0xffffffffu, Q0, 1); Q0 += __shfl_xor_sync(0xffffffffu, Q0, 2);
            S1 += __shfl_xor_sync(0xffffffffu, S1, 1); S1 += __shfl_xor_sync(0xffffffffu, S1, 2);
            Q1 += __shfl_xor_sync(0xffffffffu, Q1, 1); Q1 += __shfl_xor_sync(0xffffffffu, Q1, 2);
            if (qc == 0) {
                ps[cq*128 + R0] = S0; pq[cq*128 + R0] = Q0;
                ps[cq*128 + R1] = S1; pq[cq*128 + R1] = Q1;
            }
            __syncthreads();   // partials visible; all gather reads done
            float Sa = ps[R0] + ps[128 + R0] + ps[256 + R0] + ps[384 + R0];
            float Qa = pq[R0] + pq[128 + R0] + pq[256 + R0] + pq[384 + R0];
            float Sb = ps[R1] + ps[128 + R1] + ps[256 + R1] + ps[384 + R1];
            float Qb = pq[R1] + pq[128 + R1] + pq[256 + R1] + pq[384 + R1];
            float mu0 = Sa * (1.f/128.f), var0 = Qa * (1.f/128.f) - mu0*mu0;
            float mu1 = Sb * (1.f/128.f), var1 = Qb * (1.f/128.f) - mu1*mu1;
            float rs0 = rsqrtf(var0 + 1e-5f), rs1 = rsqrtf(var1 + 1e-5f);
#pragma unroll
            for (int nt = 0; nt < 4; ++nt) {
                int col = cb + 8*nt + 2*qc;
                float2 g2 = *(const float2*)&gg[l*128 + col];
                float2 b2 = *(const float2*)&be[l*128 + col];
                hres[nt][0] += (acc[nt][0] - mu0) * rs0 * g2.x + b2.x;
                hres[nt][1] += (acc[nt][1] - mu0) * rs0 * g2.y + b2.y;
                hres[nt][2] += (acc[nt][2] - mu1) * rs1 * g2.x + b2.x;
                hres[nt][3] += (acc[nt][3] - mu1) * rs1 * g2.y + b2.y;
            }

            if (l == 0) {
                // store h1 (tf32) as next layer's A; keep pad rows zero
#pragma unroll
                for (int nt = 0; nt < 4; ++nt) {
                    int col = cb + 8*nt + 2*qc;
                    *(uint2*)&((uint32_t*)hy)[R0*HS + col] =
                        make_uint2(f2tf32(hres[nt][0]), f2tf32(hres[nt][1]));
                    *(uint2*)&((uint32_t*)hy)[R1*HS + col] = v1
                        ? make_uint2(f2tf32(hres[nt][2]), f2tf32(hres[nt][3]))
                        : make_uint2(0u, 0u);
                }
                __syncthreads();   // h1 complete before next-layer GEMM
            } else {
                // stage final h (fp32) into hy for transposed writeback
#pragma unroll
                for (int nt = 0; nt < 4; ++nt) {
                    int col = cb + 8*nt + 2*qc;
                    *(float2*)&hy[R0*HS + col] = make_float2(hres[nt][0], hres[nt][1]);
                    if (v1)
                        *(float2*)&hy[R1*HS + col] = make_float2(hres[nt][2], hres[nt][3]);
                }
                __syncthreads();
            }
        }

        // ---- writeback: hy -> out, (pd, t)-ordered for 20B gmem chunks ----
        for (int i = tid; i < 16000; i += NT_) {
            int pd = i / 5, tl = i - pd * 5;
            int p = pd >> 7, col = pd & 127;
            ob[(size_t)pd * 120 + tl] = hy[(tl * 25 + p) * HS + col];
        }
        __syncthreads();   // out reads done before next tile restages hy
    }
}

// ---------------------------------------------------------------------------
extern "C" void kernel_launch(void* const* d_in, const int* in_sizes, int n_in,
                              void* d_out, int out_size)
{
    const float* x     = (const float*)d_in[0];
    const float* dist  = (const float*)d_in[1];
    const float* w     = (const float*)d_in[2];
    const float* bias  = (const float*)d_in[3];
    const float* gamma = (const float*)d_in[4];
    const float* beta  = (const float*)d_in[5];
    float* out = (float*)d_out;

    cudaFuncSetAttribute(k_main, cudaFuncAttributeMaxDynamicSharedMemorySize,
                         SMEM_MAIN);

    int sms = 148;
    cudaDeviceGetAttribute(&sms, cudaDevAttrMultiProcessorCount, 0);

    k_main<<<sms, NT_, SMEM_MAIN>>>(x, dist, w, bias, gamma, beta, out);
}